// round 7
// baseline (speedup 1.0000x reference)
#include <cuda_runtime.h>
#include <cuda_bf16.h>

// src [8,16,512,512] f32, flow [8,2,512,512] f32, out [8,16,512,512] f32.
//
// Index math reproduces XLA's lowering bit-exactly (reciprocal-constant rewrite
// of /511, every intermediate fp32-rounded, no FMA contraction, rint
// half-to-even, border clamp). Verified rel_err == 0.0 in R3-R6.
//
// Perf structure (R7): PERSISTENT grid-stride kernel. grid = 148 SMs x 8 CTAs
// = 1184 blocks -> exactly one wave (R6 had 7 waves and paid ~6 transitions of
// fill/drain + T_wave_trans). Each thread loops ~7 pixels; loop iterations give
// the warp cross-pixel MLP for free. 32-reg / 8 CTA/SM operating point kept.

#define B 8
#define C 16
#define H 512
#define W 512
#define HW (H * W)          // 1<<18
#define HW_BITS 18
#define W_BITS 9
#define NPIX (B * HW)       // 2,097,152

__device__ __forceinline__ int ref_index(float coord, float disp)
{
    const float rcp = 1.0f / 511.0f;         // fp32(1/511), XLA recip rewrite
    float t = __fadd_rn(coord, disp);        // ii + flow
    t = __fmul_rn(t, rcp);                   // * (1/511)
    t = __fadd_rn(t, -0.5f);                 // - 0.5
    t = __fmul_rn(2.0f, t);                  // * 2 (exact)
    t = __fadd_rn(t, 1.0f);                  // + 1
    t = __fmul_rn(t, 0.5f);                  // * 0.5 (exact)
    t = __fmul_rn(t, 511.0f);                // * 511
    int i = __float2int_rn(t);               // round half-to-even
    return min(max(i, 0), 511);              // border clamp
}

__global__ __launch_bounds__(256, 8) void flow_warp_nearest_persist_kernel(
    const float* __restrict__ src,
    const float* __restrict__ flow,
    float* __restrict__ out)
{
    const int stride = gridDim.x * blockDim.x;           // 303,104
    for (int idx = blockIdx.x * blockDim.x + threadIdx.x;
         idx < NPIX; idx += stride)
    {
        int b  = idx >> HW_BITS;
        int hw = idx & (HW - 1);
        int h  = hw >> W_BITS;
        int w  = hw & (W - 1);

        const float* fb = flow + (size_t)b * 2 * HW;
        float f0 = __ldcs(fb + hw);          // row displacement (streamed)
        float f1 = __ldcs(fb + HW + hw);     // col displacement (streamed)

        int yi = ref_index((float)h, f0);
        int xi = ref_index((float)w, f1);
        int lin = (yi << W_BITS) + xi;

        const float* sb = src + (size_t)b * C * HW;
        float*       ob = out + (size_t)b * C * HW;

        #pragma unroll
        for (int c = 0; c < C; ++c) {
            __stcs(ob + c * HW + hw, __ldg(sb + c * HW + lin));
        }
    }
}

extern "C" void kernel_launch(void* const* d_in, const int* in_sizes, int n_in,
                              void* d_out, int out_size)
{
    const float* src  = (const float*)d_in[0];
    const float* flow = (const float*)d_in[1];
    float*       out  = (float*)d_out;

    int threads = 256;
    int blocks  = 148 * 8;              // one full wave, persistent
    flow_warp_nearest_persist_kernel<<<blocks, threads>>>(src, flow, out);
}